// round 17
// baseline (speedup 1.0000x reference)
#include <cuda_runtime.h>

static constexpr int H = 512;
static constexpr int W = 512;
static constexpr unsigned FULL = 0xFFFFFFFFu;

__device__ __forceinline__ float med3f(float a, float b, float c) {
    return fmaxf(fminf(a, b), fminf(fmaxf(a, b), c));
}

// Streamed horizontal merge over 16 columns (full warp spans the 512-col row,
// so lane 0 / lane 31 halo triples are the zero-pad constant (0,0,0)).
// t = raw third row, (p,q) = vertically pre-sorted shared pair.
// Outputs stored immediately as float2 pairs (no o[] array liveness).
__device__ __forceinline__ void row_stream16(const float* t, const float* p, const float* q,
                                              bool isL, bool isR,
                                              float* __restrict__ orow, int c0) {
    // Vertical triple for local col j.
    auto trip = [&](int j, float& lo, float& md, float& hi) {
        float m = fmaxf(t[j], p[j]);
        lo = fminf(t[j], p[j]);
        hi = fmaxf(m, q[j]);
        md = fminf(m, q[j]);
    };

    // Cols 0 and 15 first — they feed the neighbor shuffles.
    float l0, m0, h0, l15, m15, h15;
    trip(0, l0, m0, h0);
    trip(15, l15, m15, h15);

    float Ll = __shfl_up_sync(FULL, l15, 1);
    float Lm = __shfl_up_sync(FULL, m15, 1);
    float Lh = __shfl_up_sync(FULL, h15, 1);
    float Rl = __shfl_down_sync(FULL, l0, 1);
    float Rm = __shfl_down_sync(FULL, m0, 1);
    float Rh = __shfl_down_sync(FULL, h0, 1);
    if (isL) { Ll = 0.f; Lm = 0.f; Lh = 0.f; }   // image left border: zero-pad triple
    if (isR) { Rl = 0.f; Rm = 0.f; Rh = 0.f; }   // image right border

    // Sliding window; pair (b,c) shared by outputs 2k and 2k+1.
    float al = Ll, am = Lm, ah = Lh;
    float bl = l0, bm = m0, bh = h0;
#pragma unroll
    for (int k = 0; k < 8; k++) {
        float cl, cm, ch, dl, dm, dh;
        if (k < 7) {
            trip(2 * k + 1, cl, cm, ch);
            trip(2 * k + 2, dl, dm, dh);
        } else {
            cl = l15; cm = m15; ch = h15;        // col 15 (precomputed)
            dl = Rl;  dm = Rm;  dh = Rh;         // right neighbor / border
        }
        float pxl = fmaxf(bl, cl), pzl = fminf(bh, ch);
        float mn = fminf(bm, cm),  mx = fmaxf(bm, cm);
        float X0 = fmaxf(al, pxl), Z0 = fminf(ah, pzl), Y0 = fmaxf(mn, fminf(mx, am));
        float X1 = fmaxf(pxl, dl), Z1 = fminf(pzl, dh), Y1 = fmaxf(mn, fminf(mx, dm));
        float2 ov = make_float2(med3f(X0, Y0, Z0), med3f(X1, Y1, Z1));
        *(float2*)(orow + c0 + 2 * k) = ov;
        al = cl; am = cm; ah = ch;               // rotate (pure renaming when unrolled)
        bl = dl; bm = dm; bh = dh;
    }
}

__global__ __launch_bounds__(128)
void median3x3_kernel(const float* __restrict__ in, float* __restrict__ out, int nimg) {
    const int gwarp = (blockIdx.x * blockDim.x + threadIdx.x) >> 5;
    const int lane = threadIdx.x & 31;

    // Warp = 2 output rows x full 512-col row; 256 row-pairs per image.
    const int img = gwarp >> 8;
    if (img >= nimg) return;
    const int y0 = (gwarp & 255) << 1;               // 0,2,...,510
    const int c0 = lane << 4;                        // 16 columns per lane

    const float* __restrict__ base = in + (size_t)img * (H * W);
    float* __restrict__ obase = out + (size_t)img * (H * W);

    const bool topOK = (y0 > 0);
    const bool botOK = (y0 + 2 < H);
    const bool isL = (lane == 0);
    const bool isR = (lane == 31);
    const float4 z4 = make_float4(0.f, 0.f, 0.f, 0.f);

    // ---- Front-batched loads: 4 input rows (y0-1..y0+2) x 4 float4 = 16 LDG.128 ----
    const float* pA = base + (y0 - 1) * W + c0;
    const float* pB = base + (y0    ) * W + c0;
    const float* pC = base + (y0 + 1) * W + c0;
    const float* pD = base + (y0 + 2) * W + c0;
    float4 va0 = topOK ? *(const float4*)(pA)      : z4;
    float4 va1 = topOK ? *(const float4*)(pA + 4)  : z4;
    float4 va2 = topOK ? *(const float4*)(pA + 8)  : z4;
    float4 va3 = topOK ? *(const float4*)(pA + 12) : z4;
    float4 vb0 = *(const float4*)(pB);
    float4 vb1 = *(const float4*)(pB + 4);
    float4 vb2 = *(const float4*)(pB + 8);
    float4 vb3 = *(const float4*)(pB + 12);
    float4 vc0 = *(const float4*)(pC);
    float4 vc1 = *(const float4*)(pC + 4);
    float4 vc2 = *(const float4*)(pC + 8);
    float4 vc3 = *(const float4*)(pC + 12);
    float4 vd0 = botOK ? *(const float4*)(pD)      : z4;
    float4 vd1 = botOK ? *(const float4*)(pD + 4)  : z4;
    float4 vd2 = botOK ? *(const float4*)(pD + 8)  : z4;
    float4 vd3 = botOK ? *(const float4*)(pD + 12) : z4;

    float A[16] = {va0.x, va0.y, va0.z, va0.w, va1.x, va1.y, va1.z, va1.w,
                   va2.x, va2.y, va2.z, va2.w, va3.x, va3.y, va3.z, va3.w};
    float D[16] = {vd0.x, vd0.y, vd0.z, vd0.w, vd1.x, vd1.y, vd1.z, vd1.w,
                   vd2.x, vd2.y, vd2.z, vd2.w, vd3.x, vd3.y, vd3.z, vd3.w};

    // ---- Shared vertical pair (B,C); rows B,C die here ----
    float p[16], q[16];
    {
        float Bv[16] = {vb0.x, vb0.y, vb0.z, vb0.w, vb1.x, vb1.y, vb1.z, vb1.w,
                        vb2.x, vb2.y, vb2.z, vb2.w, vb3.x, vb3.y, vb3.z, vb3.w};
        float Cv[16] = {vc0.x, vc0.y, vc0.z, vc0.w, vc1.x, vc1.y, vc1.z, vc1.w,
                        vc2.x, vc2.y, vc2.z, vc2.w, vc3.x, vc3.y, vc3.z, vc3.w};
#pragma unroll
        for (int i = 0; i < 16; i++) {
            p[i] = fminf(Bv[i], Cv[i]);
            q[i] = fmaxf(Bv[i], Cv[i]);
        }
    }

    // Row y0 = median(A, B, C); row y0+1 = median(B, C, D).
    row_stream16(A, p, q, isL, isR, obase + (y0    ) * W, c0);
    row_stream16(D, p, q, isL, isR, obase + (y0 + 1) * W, c0);
}

extern "C" void kernel_launch(void* const* d_in, const int* in_sizes, int n_in,
                              void* d_out, int out_size) {
    const float* x = (const float*)d_in[0];
    float* y = (float*)d_out;
    const int nimg = in_sizes[0] / (H * W);           // B*C images
    const int warps = nimg * (H / 2);                 // one warp per row-pair
    const int threads = warps * 32;
    const int block = 128;
    const int grid = (threads + block - 1) / block;
    median3x3_kernel<<<grid, block>>>(x, y, nimg);
}